// round 1
// baseline (speedup 1.0000x reference)
#include <cuda_runtime.h>
#include <math.h>

#define N 4096
#define D 1024
#define NCB 32              // 4096 / 128 column blocks

// Scratch (allocation-free rule: __device__ globals).
// Partial row reductions: slot [colBlk*N + row] written by exactly one thread
// -> fully deterministic, no atomics anywhere.
__device__ float g_sq  [N];
__device__ float g_posl[NCB * N];
__device__ float g_negl[NCB * N];
__device__ float g_poss[NCB * N];
__device__ float g_negs[NCB * N];
__device__ float g_posd[NCB * N];
__device__ float g_negd[NCB * N];
__device__ float g_pcnt[NCB * N];

// ---------------------------------------------------------------------------
// Kernel 1: squared row norms (one warp per row)
// ---------------------------------------------------------------------------
__global__ void k_sq(const float* __restrict__ X) {
    int warp = (blockIdx.x * blockDim.x + threadIdx.x) >> 5;
    int lane = threadIdx.x & 31;
    if (warp >= N) return;
    const float4* row = (const float4*)(X + (size_t)warp * D);
    float s = 0.f;
#pragma unroll
    for (int it = 0; it < D / 128; ++it) {
        float4 v = row[lane + it * 32];
        s += v.x * v.x + v.y * v.y + v.z * v.z + v.w * v.w;
    }
#pragma unroll
    for (int o = 16; o; o >>= 1) s += __shfl_xor_sync(0xffffffffu, s, o);
    if (lane == 0) g_sq[warp] = s;
}

// ---------------------------------------------------------------------------
// Kernel 2: fused 128x128 tile SGEMM (X @ X^T) + A-HardPair epilogue.
// blockIdx.x = j tile (col block), blockIdx.y = i tile (row block).
// 256 threads, each owns an 8x8 micro-tile. Double-buffered smem, BK=16.
// ---------------------------------------------------------------------------
__global__ __launch_bounds__(256, 2)
void k_main(const float* __restrict__ X, const int* __restrict__ T) {
    __shared__ float As[2][16][128];
    __shared__ float Bs[2][16][128];

    const int tid = threadIdx.x;
    const int tx = tid & 15;          // j sub-tile
    const int ty = tid >> 4;          // i sub-tile
    const int i0 = blockIdx.y * 128;
    const int j0 = blockIdx.x * 128;

    const int lrow = tid >> 2;        // 0..63 (and +64)
    const int lk   = (tid & 3) * 4;   // 0,4,8,12

    const float* Ap = X + (size_t)(i0 + lrow) * D + lk;
    const float* Bp = X + (size_t)(j0 + lrow) * D + lk;

    float C[8][8];
#pragma unroll
    for (int a = 0; a < 8; ++a)
#pragma unroll
        for (int b = 0; b < 8; ++b) C[a][b] = 0.f;

    // Prologue: stage 0
    {
        float4 a0 = *(const float4*)(Ap);
        float4 a1 = *(const float4*)(Ap + (size_t)64 * D);
        float4 b0 = *(const float4*)(Bp);
        float4 b1 = *(const float4*)(Bp + (size_t)64 * D);
#pragma unroll
        for (int c = 0; c < 4; ++c) {
            As[0][lk + c][lrow]      = ((const float*)&a0)[c];
            As[0][lk + c][lrow + 64] = ((const float*)&a1)[c];
            Bs[0][lk + c][lrow]      = ((const float*)&b0)[c];
            Bs[0][lk + c][lrow + 64] = ((const float*)&b1)[c];
        }
    }
    __syncthreads();

    int buf = 0;
#pragma unroll 1
    for (int t = 0; t < D / 16; ++t) {
        float4 na0, na1, nb0, nb1;
        const bool has_next = (t < D / 16 - 1);
        if (has_next) {
            const float* Ap2 = Ap + (t + 1) * 16;
            const float* Bp2 = Bp + (t + 1) * 16;
            na0 = *(const float4*)(Ap2);
            na1 = *(const float4*)(Ap2 + (size_t)64 * D);
            nb0 = *(const float4*)(Bp2);
            nb1 = *(const float4*)(Bp2 + (size_t)64 * D);
        }
#pragma unroll
        for (int kk = 0; kk < 16; ++kk) {
            float af[8], bf[8];
            *(float4*)(af)     = *(const float4*)&As[buf][kk][ty * 8];
            *(float4*)(af + 4) = *(const float4*)&As[buf][kk][ty * 8 + 4];
            *(float4*)(bf)     = *(const float4*)&Bs[buf][kk][tx * 8];
            *(float4*)(bf + 4) = *(const float4*)&Bs[buf][kk][tx * 8 + 4];
#pragma unroll
            for (int a = 0; a < 8; ++a)
#pragma unroll
                for (int b = 0; b < 8; ++b)
                    C[a][b] = fmaf(af[a], bf[b], C[a][b]);
        }
        if (has_next) {
            buf ^= 1;
#pragma unroll
            for (int c = 0; c < 4; ++c) {
                As[buf][lk + c][lrow]      = ((const float*)&na0)[c];
                As[buf][lk + c][lrow + 64] = ((const float*)&na1)[c];
                Bs[buf][lk + c][lrow]      = ((const float*)&nb0)[c];
                Bs[buf][lk + c][lrow + 64] = ((const float*)&nb1)[c];
            }
            __syncthreads();
        }
    }

    // ---- Epilogue: dist -> masked exp sums, reduce over the 128 j's -------
    float sqj[8];
    int   tj[8];
#pragma unroll
    for (int b = 0; b < 8; ++b) {
        sqj[b] = g_sq[j0 + tx * 8 + b];
        tj[b]  = T[j0 + tx * 8 + b];
    }

#pragma unroll
    for (int a = 0; a < 8; ++a) {
        const int gi = i0 + ty * 8 + a;
        const float sqi = g_sq[gi];
        const int ti = T[gi];
        float posl = 0.f, negl = 0.f, poss = 0.f, negs = 0.f;
        float posd = 0.f, negd = 0.f, cnt = 0.f;
#pragma unroll
        for (int b = 0; b < 8; ++b) {
            const int gj = j0 + tx * 8 + b;
            if (gi == gj) continue;                      // ~eye
            float d2   = sqi + sqj[b] - 2.f * C[a][b];
            float dist = sqrtf(fmaxf(d2, 1e-12f));
            float ea   = __expf(40.f * (1.f - dist));
            if (ti == tj[b]) {                            // positive pair
                posl += ea;
                poss += __expf(20.f * (dist - 0.8f));
                posd += dist;
                cnt  += 1.f;
            } else {                                      // negative pair
                negl += ea;
                negs += __expf(20.f * (1.1f - dist));
                negd += dist;
            }
        }
        // Reduce across the 16 tx lanes (xor offsets < 16 stay in half-warp).
#pragma unroll
        for (int o = 8; o; o >>= 1) {
            posl += __shfl_xor_sync(0xffffffffu, posl, o);
            negl += __shfl_xor_sync(0xffffffffu, negl, o);
            poss += __shfl_xor_sync(0xffffffffu, poss, o);
            negs += __shfl_xor_sync(0xffffffffu, negs, o);
            posd += __shfl_xor_sync(0xffffffffu, posd, o);
            negd += __shfl_xor_sync(0xffffffffu, negd, o);
            cnt  += __shfl_xor_sync(0xffffffffu, cnt,  o);
        }
        if (tx == 0) {
            const int idx = blockIdx.x * N + gi;          // unique slot
            g_posl[idx] = posl;  g_negl[idx] = negl;
            g_poss[idx] = poss;  g_negs[idx] = negs;
            g_posd[idx] = posd;  g_negd[idx] = negd;
            g_pcnt[idx] = cnt;
        }
    }
}

// ---------------------------------------------------------------------------
// Kernel 3: fold 32 partials per row, compute loss/pos_d/neg_d, write out[4].
// ---------------------------------------------------------------------------
__global__ void k_final(float* __restrict__ out) {
    __shared__ double sh[4][32];
    double lsum = 0.0, pd = 0.0, nd = 0.0, pc = 0.0;

    for (int i = threadIdx.x; i < N; i += blockDim.x) {
        float posl = 0.f, negl = 0.f, poss = 0.f, negs = 0.f;
        float posd = 0.f, negd = 0.f, cnt = 0.f;
#pragma unroll
        for (int c = 0; c < NCB; ++c) {
            const int idx = c * N + i;
            posl += g_posl[idx]; negl += g_negl[idx];
            poss += g_poss[idx]; negs += g_negs[idx];
            posd += g_posd[idx]; negd += g_negd[idx];
            cnt  += g_pcnt[idx];
        }
        float a_lr = 1.f - posl / (posl + negl);
        lsum += (double)(a_lr * (logf(poss) + logf(negs)));
        pd += (double)posd;
        nd += (double)negd;
        pc += (double)cnt;
    }
#pragma unroll
    for (int o = 16; o; o >>= 1) {
        lsum += __shfl_xor_sync(0xffffffffu, lsum, o);
        pd   += __shfl_xor_sync(0xffffffffu, pd,   o);
        nd   += __shfl_xor_sync(0xffffffffu, nd,   o);
        pc   += __shfl_xor_sync(0xffffffffu, pc,   o);
    }
    const int lane = threadIdx.x & 31;
    const int w    = threadIdx.x >> 5;
    if (lane == 0) { sh[0][w] = lsum; sh[1][w] = pd; sh[2][w] = nd; sh[3][w] = pc; }
    __syncthreads();
    if (threadIdx.x == 0) {
        double L = 0.0, P = 0.0, Nd = 0.0, Pc = 0.0;
        const int nw = blockDim.x >> 5;
        for (int k = 0; k < nw; ++k) {
            L += sh[0][k]; P += sh[1][k]; Nd += sh[2][k]; Pc += sh[3][k];
        }
        double negcnt = (double)N * (double)(N - 1) - Pc;
        out[0] = (float)(L / (double)N);
        out[1] = 0.f;
        out[2] = (float)(P / Pc);
        out[3] = (float)(Nd / negcnt);
    }
}

// ---------------------------------------------------------------------------
extern "C" void kernel_launch(void* const* d_in, const int* in_sizes, int n_in,
                              void* d_out, int out_size) {
    const float* X = (const float*)d_in[0];   // [4096,1024] fp32, L2-normalized
    const int*   T = (const int*)d_in[1];     // [4096] int32 targets
    float* out = (float*)d_out;               // [4] fp32

    k_sq<<<N / 8, 256>>>(X);
    dim3 grid(NCB, NCB);
    k_main<<<grid, 256>>>(X, T);
    k_final<<<1, 1024>>>(out);
}

// round 11
// speedup vs baseline: 2.6616x; 2.6616x over previous
#include <cuda_runtime.h>
#include <math.h>
#include <stdint.h>

#define N 4096
#define D 1024
#define NCB 32              // 4096 / 128 column blocks
#define NRB 16              // row-reduction blocks

// Scratch (allocation-free rule: __device__ globals).
__device__ float g_sq  [N];
__device__ float g_posl[NCB * N];
__device__ float g_negl[NCB * N];
__device__ float g_poss[NCB * N];
__device__ float g_negs[NCB * N];
__device__ float g_posd[NCB * N];
__device__ float g_negd[NCB * N];
__device__ float g_pcnt[NCB * N];
__device__ double g_blk[NRB][4];

__device__ __forceinline__ uint32_t f2tf32(float f) {
    uint32_t u;
    asm("cvt.rna.tf32.f32 %0, %1;" : "=r"(u) : "f"(f));
    return u;
}
__device__ __forceinline__ float fast_sqrt(float x) {
    float y;
    asm("sqrt.approx.f32 %0, %1;" : "=f"(y) : "f"(x));
    return y;
}
__device__ __forceinline__ void mma_tf32(float c[4], uint32_t a0, uint32_t a1,
                                         uint32_t a2, uint32_t a3,
                                         uint32_t b0, uint32_t b1) {
    asm volatile(
        "mma.sync.aligned.m16n8k8.row.col.f32.tf32.tf32.f32 "
        "{%0,%1,%2,%3}, {%4,%5,%6,%7}, {%8,%9}, {%0,%1,%2,%3};\n"
        : "+f"(c[0]), "+f"(c[1]), "+f"(c[2]), "+f"(c[3])
        : "r"(a0), "r"(a1), "r"(a2), "r"(a3), "r"(b0), "r"(b1));
}

// ---------------------------------------------------------------------------
// Kernel 1: squared row norms (one warp per row)
// ---------------------------------------------------------------------------
__global__ void k_sq(const float* __restrict__ X) {
    int warp = (blockIdx.x * blockDim.x + threadIdx.x) >> 5;
    int lane = threadIdx.x & 31;
    if (warp >= N) return;
    const float4* row = (const float4*)(X + (size_t)warp * D);
    float s = 0.f;
#pragma unroll
    for (int it = 0; it < D / 128; ++it) {
        float4 v = row[lane + it * 32];
        s += v.x * v.x + v.y * v.y + v.z * v.z + v.w * v.w;
    }
#pragma unroll
    for (int o = 16; o; o >>= 1) s += __shfl_xor_sync(0xffffffffu, s, o);
    if (lane == 0) g_sq[warp] = s;
}

// ---------------------------------------------------------------------------
// Kernel 2: tf32 tensor-core 128x128 tile GEMM (X @ X^T) + fused epilogue.
// 256 threads = 8 warps in a 4(row) x 2(col) grid; warp tile 32x64;
// per warp per k8-step: 2 m-tiles x 8 n-tiles of m16n8k8 mma.
// smem: [m][k] tiles, row stride 20 (conflict-free fragment loads).
// ---------------------------------------------------------------------------
#define BK 16
#define SAS 20              // smem row stride in floats

__global__ __launch_bounds__(256, 2)
void k_main(const float* __restrict__ X, const int* __restrict__ T) {
    __shared__ __align__(16) char raw[41216];
    uint32_t (*As)[128][SAS] = (uint32_t(*)[128][SAS])(raw);           // [2][128][20]
    uint32_t (*Bs)[128][SAS] = (uint32_t(*)[128][SAS])(raw + 20480);   // [2][128][20]

    const int tid = threadIdx.x;
    const int wid = tid >> 5;
    const int lane = tid & 31;
    const int qr = lane >> 2;         // 0..7
    const int qc = lane & 3;          // 0..3
    const int warp_row = wid & 3;     // 0..3 -> 32-row slab
    const int warp_col = wid >> 2;    // 0..1 -> 64-col slab
    const int i0 = blockIdx.y * 128;
    const int j0 = blockIdx.x * 128;

    const int lrow = tid >> 2;        // 0..63
    const int lk   = (tid & 3) * 4;   // 0,4,8,12

    const float* Ap = X + (size_t)(i0 + lrow) * D + lk;
    const float* Bp = X + (size_t)(j0 + lrow) * D + lk;

    float C[2][8][4];
#pragma unroll
    for (int mt = 0; mt < 2; ++mt)
#pragma unroll
        for (int nt = 0; nt < 8; ++nt)
#pragma unroll
            for (int r = 0; r < 4; ++r) C[mt][nt][r] = 0.f;

    // Prologue: stage 0
    {
        float4 a0 = *(const float4*)(Ap);
        float4 a1 = *(const float4*)(Ap + (size_t)64 * D);
        float4 b0 = *(const float4*)(Bp);
        float4 b1 = *(const float4*)(Bp + (size_t)64 * D);
        uint4 ua0 = {f2tf32(a0.x), f2tf32(a0.y), f2tf32(a0.z), f2tf32(a0.w)};
        uint4 ua1 = {f2tf32(a1.x), f2tf32(a1.y), f2tf32(a1.z), f2tf32(a1.w)};
        uint4 ub0 = {f2tf32(b0.x), f2tf32(b0.y), f2tf32(b0.z), f2tf32(b0.w)};
        uint4 ub1 = {f2tf32(b1.x), f2tf32(b1.y), f2tf32(b1.z), f2tf32(b1.w)};
        *(uint4*)&As[0][lrow][lk]      = ua0;
        *(uint4*)&As[0][lrow + 64][lk] = ua1;
        *(uint4*)&Bs[0][lrow][lk]      = ub0;
        *(uint4*)&Bs[0][lrow + 64][lk] = ub1;
    }
    __syncthreads();

    int buf = 0;
#pragma unroll 1
    for (int t = 0; t < D / BK; ++t) {
        float4 na0, na1, nb0, nb1;
        const bool has_next = (t < D / BK - 1);
        if (has_next) {
            const float* Ap2 = Ap + (t + 1) * BK;
            const float* Bp2 = Bp + (t + 1) * BK;
            na0 = *(const float4*)(Ap2);
            na1 = *(const float4*)(Ap2 + (size_t)64 * D);
            nb0 = *(const float4*)(Bp2);
            nb1 = *(const float4*)(Bp2 + (size_t)64 * D);
        }
#pragma unroll
        for (int k0 = 0; k0 < BK; k0 += 8) {
            uint32_t af[2][4];
#pragma unroll
            for (int mt = 0; mt < 2; ++mt) {
                const int m = warp_row * 32 + mt * 16;
                af[mt][0] = As[buf][m + qr][k0 + qc];
                af[mt][1] = As[buf][m + qr + 8][k0 + qc];
                af[mt][2] = As[buf][m + qr][k0 + qc + 4];
                af[mt][3] = As[buf][m + qr + 8][k0 + qc + 4];
            }
            uint32_t bf[8][2];
#pragma unroll
            for (int nt = 0; nt < 8; ++nt) {
                const int n = warp_col * 64 + nt * 8;
                bf[nt][0] = Bs[buf][n + qr][k0 + qc];
                bf[nt][1] = Bs[buf][n + qr][k0 + qc + 4];
            }
#pragma unroll
            for (int mt = 0; mt < 2; ++mt)
#pragma unroll
                for (int nt = 0; nt < 8; ++nt)
                    mma_tf32(C[mt][nt], af[mt][0], af[mt][1], af[mt][2],
                             af[mt][3], bf[nt][0], bf[nt][1]);
        }
        if (has_next) {
            buf ^= 1;
            uint4 ua0 = {f2tf32(na0.x), f2tf32(na0.y), f2tf32(na0.z), f2tf32(na0.w)};
            uint4 ua1 = {f2tf32(na1.x), f2tf32(na1.y), f2tf32(na1.z), f2tf32(na1.w)};
            uint4 ub0 = {f2tf32(nb0.x), f2tf32(nb0.y), f2tf32(nb0.z), f2tf32(nb0.w)};
            uint4 ub1 = {f2tf32(nb1.x), f2tf32(nb1.y), f2tf32(nb1.z), f2tf32(nb1.w)};
            __syncthreads();                 // all reads of buf^1 done
            *(uint4*)&As[buf][lrow][lk]      = ua0;
            *(uint4*)&As[buf][lrow + 64][lk] = ua1;
            *(uint4*)&Bs[buf][lrow][lk]      = ub0;
            *(uint4*)&Bs[buf][lrow + 64][lk] = ub1;
            __syncthreads();
        }
    }

    // ---- Epilogue --------------------------------------------------------
    __syncthreads();   // done with GEMM smem; overlay epilogue buffers
    float (*part)[128][8] = (float(*)[128][8])raw;          // [2][128][8] = 8192B
    float* SqI = (float*)(raw + 8192);                      // 128 floats
    float* SqJ = SqI + 128;                                 // 128 floats
    int*   TgI = (int*)(raw + 9216);                        // 128 ints
    int*   TgJ = TgI + 128;                                 // 128 ints

    if (tid < 128) { SqI[tid] = g_sq[i0 + tid]; TgI[tid] = T[i0 + tid]; }
    else { int r = tid - 128; SqJ[r] = g_sq[j0 + r]; TgJ[r] = T[j0 + r]; }
    __syncthreads();

    // Preload the 16 column attributes this thread touches.
    float sqj[16]; int tj[16]; int colv[16];
#pragma unroll
    for (int nt = 0; nt < 8; ++nt)
#pragma unroll
        for (int e = 0; e < 2; ++e) {
            const int c = warp_col * 64 + nt * 8 + qc * 2 + e;
            colv[nt * 2 + e] = c;
            sqj[nt * 2 + e] = SqJ[c];
            tj[nt * 2 + e] = TgJ[c];
        }

#pragma unroll
    for (int mt = 0; mt < 2; ++mt)
#pragma unroll
        for (int rh = 0; rh < 2; ++rh) {
            const int row = warp_row * 32 + mt * 16 + rh * 8 + qr;
            const int gi = i0 + row;
            const float sqi = SqI[row];
            const int ti = TgI[row];
            float posl = 0.f, negl = 0.f, poss = 0.f, negs = 0.f;
            float posd = 0.f, negd = 0.f, cnt = 0.f;
#pragma unroll
            for (int q = 0; q < 16; ++q) {
                const int nt = q >> 1, e = q & 1;
                const int gj = j0 + colv[q];
                if (gi == gj) continue;
                const float dot = C[mt][nt][rh * 2 + e];
                float d2 = sqi + sqj[q] - 2.f * dot;
                float dist = fast_sqrt(fmaxf(d2, 1e-12f));
                float ea = __expf(40.f * (1.f - dist));
                if (ti == tj[q]) {
                    posl += ea;
                    poss += __expf(20.f * (dist - 0.8f));
                    posd += dist;
                    cnt += 1.f;
                } else {
                    negl += ea;
                    negs += __expf(20.f * (1.1f - dist));
                    negd += dist;
                }
            }
#pragma unroll
            for (int o = 1; o <= 2; o <<= 1) {
                posl += __shfl_xor_sync(0xffffffffu, posl, o);
                negl += __shfl_xor_sync(0xffffffffu, negl, o);
                poss += __shfl_xor_sync(0xffffffffu, poss, o);
                negs += __shfl_xor_sync(0xffffffffu, negs, o);
                posd += __shfl_xor_sync(0xffffffffu, posd, o);
                negd += __shfl_xor_sync(0xffffffffu, negd, o);
                cnt  += __shfl_xor_sync(0xffffffffu, cnt,  o);
            }
            if (qc == 0) {
                part[warp_col][row][0] = posl;
                part[warp_col][row][1] = negl;
                part[warp_col][row][2] = poss;
                part[warp_col][row][3] = negs;
                part[warp_col][row][4] = posd;
                part[warp_col][row][5] = negd;
                part[warp_col][row][6] = cnt;
            }
        }
    __syncthreads();

    if (tid < 128) {
        const int row = tid;
        const int idx = blockIdx.x * N + (i0 + row);
        g_posl[idx] = part[0][row][0] + part[1][row][0];
        g_negl[idx] = part[0][row][1] + part[1][row][1];
        g_poss[idx] = part[0][row][2] + part[1][row][2];
        g_negs[idx] = part[0][row][3] + part[1][row][3];
        g_posd[idx] = part[0][row][4] + part[1][row][4];
        g_negd[idx] = part[0][row][5] + part[1][row][5];
        g_pcnt[idx] = part[0][row][6] + part[1][row][6];
    }
}

// ---------------------------------------------------------------------------
// Kernel 3a: per-row fold of the 32 column-block partials (16 blocks x 256).
// One thread per row; block-reduces the 4 outputs in double -> g_blk slot.
// ---------------------------------------------------------------------------
__global__ void k_rows(void) {
    __shared__ double sh[4][8];
    const int i = blockIdx.x * 256 + threadIdx.x;   // row id, 0..4095

    float posl = 0.f, negl = 0.f, poss = 0.f, negs = 0.f;
    float posd = 0.f, negd = 0.f, cnt = 0.f;
#pragma unroll
    for (int c = 0; c < NCB; ++c) {
        const int idx = c * N + i;
        posl += g_posl[idx]; negl += g_negl[idx];
        poss += g_poss[idx]; negs += g_negs[idx];
        posd += g_posd[idx]; negd += g_negd[idx];
        cnt  += g_pcnt[idx];
    }
    float a_lr = 1.f - posl / (posl + negl);
    double lsum = (double)(a_lr * (logf(poss) + logf(negs)));
    double pd = (double)posd, nd = (double)negd, pc = (double)cnt;

#pragma unroll
    for (int o = 16; o; o >>= 1) {
        lsum += __shfl_xor_sync(0xffffffffu, lsum, o);
        pd   += __shfl_xor_sync(0xffffffffu, pd,   o);
        nd   += __shfl_xor_sync(0xffffffffu, nd,   o);
        pc   += __shfl_xor_sync(0xffffffffu, pc,   o);
    }
    const int lane = threadIdx.x & 31;
    const int w    = threadIdx.x >> 5;
    if (lane == 0) { sh[0][w] = lsum; sh[1][w] = pd; sh[2][w] = nd; sh[3][w] = pc; }
    __syncthreads();
    if (threadIdx.x == 0) {
        double L = 0.0, P = 0.0, Nd = 0.0, Pc = 0.0;
#pragma unroll
        for (int k = 0; k < 8; ++k) {
            L += sh[0][k]; P += sh[1][k]; Nd += sh[2][k]; Pc += sh[3][k];
        }
        g_blk[blockIdx.x][0] = L;
        g_blk[blockIdx.x][1] = P;
        g_blk[blockIdx.x][2] = Nd;
        g_blk[blockIdx.x][3] = Pc;
    }
}

// ---------------------------------------------------------------------------
// Kernel 3b: fold the 16 block partials, write out[4].
// ---------------------------------------------------------------------------
__global__ void k_final4(float* __restrict__ out) {
    if (threadIdx.x == 0) {
        double L = 0.0, P = 0.0, Nd = 0.0, Pc = 0.0;
#pragma unroll
        for (int k = 0; k < NRB; ++k) {
            L += g_blk[k][0]; P += g_blk[k][1]; Nd += g_blk[k][2]; Pc += g_blk[k][3];
        }
        double negcnt = (double)N * (double)(N - 1) - Pc;
        out[0] = (float)(L / (double)N);
        out[1] = 0.f;
        out[2] = (float)(P / Pc);
        out[3] = (float)(Nd / negcnt);
    }
}

// ---------------------------------------------------------------------------
extern "C" void kernel_launch(void* const* d_in, const int* in_sizes, int n_in,
                              void* d_out, int out_size) {
    const float* X = (const float*)d_in[0];   // [4096,1024] fp32, L2-normalized
    const int*   T = (const int*)d_in[1];     // [4096] int32 targets
    float* out = (float*)d_out;               // [4] fp32

    k_sq<<<N / 8, 256>>>(X);
    dim3 grid(NCB, NCB);
    k_main<<<grid, 256>>>(X, T);
    k_rows<<<NRB, 256>>>();
    k_final4<<<1, 32>>>(out);
}

// round 12
// speedup vs baseline: 4.0429x; 1.5189x over previous
#include <cuda_runtime.h>
#include <math.h>
#include <stdint.h>

#define N 4096
#define D 1024
#define NCB 32              // 4096 / 128 column blocks
#define NRB 16              // row-reduction blocks

// Scratch (allocation-free rule: __device__ globals).
__device__ float g_sq  [N];
__device__ float g_posl[NCB * N];
__device__ float g_negl[NCB * N];
__device__ float g_poss[NCB * N];
__device__ float g_negs[NCB * N];
__device__ float g_posd[NCB * N];
__device__ float g_negd[NCB * N];
__device__ float g_pcnt[NCB * N];
__device__ double g_blk[NRB][4];

// Pack two fp32 -> bf16x2 (lo = first arg position in memory order).
// PTX: cvt.rn.bf16x2.f32 d, a, b  ->  d.hi = bf16(a), d.lo = bf16(b)
__device__ __forceinline__ uint32_t f2bf16x2(float lo, float hi) {
    uint32_t u;
    asm("cvt.rn.bf16x2.f32 %0, %1, %2;" : "=r"(u) : "f"(hi), "f"(lo));
    return u;
}
__device__ __forceinline__ float fast_sqrt(float x) {
    float y;
    asm("sqrt.approx.f32 %0, %1;" : "=f"(y) : "f"(x));
    return y;
}
// m16n8k16 bf16 mma, fp32 accumulate.
__device__ __forceinline__ void mma_bf16(float c[4], uint32_t a0, uint32_t a1,
                                         uint32_t a2, uint32_t a3,
                                         uint32_t b0, uint32_t b1) {
    asm volatile(
        "mma.sync.aligned.m16n8k16.row.col.f32.bf16.bf16.f32 "
        "{%0,%1,%2,%3}, {%4,%5,%6,%7}, {%8,%9}, {%0,%1,%2,%3};\n"
        : "+f"(c[0]), "+f"(c[1]), "+f"(c[2]), "+f"(c[3])
        : "r"(a0), "r"(a1), "r"(a2), "r"(a3), "r"(b0), "r"(b1));
}

// ---------------------------------------------------------------------------
// Kernel 1: squared row norms (one warp per row)
// ---------------------------------------------------------------------------
__global__ void k_sq(const float* __restrict__ X) {
    int warp = (blockIdx.x * blockDim.x + threadIdx.x) >> 5;
    int lane = threadIdx.x & 31;
    if (warp >= N) return;
    const float4* row = (const float4*)(X + (size_t)warp * D);
    float s = 0.f;
#pragma unroll
    for (int it = 0; it < D / 128; ++it) {
        float4 v = row[lane + it * 32];
        s += v.x * v.x + v.y * v.y + v.z * v.z + v.w * v.w;
    }
#pragma unroll
    for (int o = 16; o; o >>= 1) s += __shfl_xor_sync(0xffffffffu, s, o);
    if (lane == 0) g_sq[warp] = s;
}

// ---------------------------------------------------------------------------
// Kernel 2: bf16 tensor-core 128x128 tile GEMM (X @ X^T) + fused epilogue.
// 256 threads = 8 warps, 4(row) x 2(col); warp tile 32x64;
// per BK=16 k-slab: one m16n8k16 k-step, 2 m-tiles x 8 n-tiles per warp.
// smem: packed bf16x2, [128][12] uint32 rows (8 data + 4 pad; qr*12+qc
// distinct mod 32 -> conflict-free fragment loads).
// ---------------------------------------------------------------------------
#define BK 16
#define SAS 12              // smem row stride in uint32 (bf16 pairs)

__global__ __launch_bounds__(256, 2)
void k_main(const float* __restrict__ X, const int* __restrict__ T) {
    __shared__ __align__(16) char raw[24576];
    uint32_t (*As)[128][SAS] = (uint32_t(*)[128][SAS])(raw);           // [2][128][12]
    uint32_t (*Bs)[128][SAS] = (uint32_t(*)[128][SAS])(raw + 12288);   // [2][128][12]

    const int tid = threadIdx.x;
    const int wid = tid >> 5;
    const int lane = tid & 31;
    const int qr = lane >> 2;         // 0..7
    const int qc = lane & 3;          // 0..3
    const int warp_row = wid & 3;     // 0..3 -> 32-row slab
    const int warp_col = wid >> 2;    // 0..1 -> 64-col slab
    const int i0 = blockIdx.y * 128;
    const int j0 = blockIdx.x * 128;

    const int lrow = tid >> 2;        // 0..63
    const int lk   = (tid & 3) * 4;   // float offset 0,4,8,12
    const int lp   = (tid & 3) * 2;   // packed offset 0,2,4,6

    const float* Ap = X + (size_t)(i0 + lrow) * D + lk;
    const float* Bp = X + (size_t)(j0 + lrow) * D + lk;

    float C[2][8][4];
#pragma unroll
    for (int mt = 0; mt < 2; ++mt)
#pragma unroll
        for (int nt = 0; nt < 8; ++nt)
#pragma unroll
            for (int r = 0; r < 4; ++r) C[mt][nt][r] = 0.f;

    // Prologue: stage 0
    {
        float4 a0 = *(const float4*)(Ap);
        float4 a1 = *(const float4*)(Ap + (size_t)64 * D);
        float4 b0 = *(const float4*)(Bp);
        float4 b1 = *(const float4*)(Bp + (size_t)64 * D);
        As[0][lrow][lp]          = f2bf16x2(a0.x, a0.y);
        As[0][lrow][lp + 1]      = f2bf16x2(a0.z, a0.w);
        As[0][lrow + 64][lp]     = f2bf16x2(a1.x, a1.y);
        As[0][lrow + 64][lp + 1] = f2bf16x2(a1.z, a1.w);
        Bs[0][lrow][lp]          = f2bf16x2(b0.x, b0.y);
        Bs[0][lrow][lp + 1]      = f2bf16x2(b0.z, b0.w);
        Bs[0][lrow + 64][lp]     = f2bf16x2(b1.x, b1.y);
        Bs[0][lrow + 64][lp + 1] = f2bf16x2(b1.z, b1.w);
    }
    __syncthreads();

    int buf = 0;
#pragma unroll 1
    for (int t = 0; t < D / BK; ++t) {
        float4 na0, na1, nb0, nb1;
        const bool has_next = (t < D / BK - 1);
        if (has_next) {
            const float* Ap2 = Ap + (t + 1) * BK;
            const float* Bp2 = Bp + (t + 1) * BK;
            na0 = *(const float4*)(Ap2);
            na1 = *(const float4*)(Ap2 + (size_t)64 * D);
            nb0 = *(const float4*)(Bp2);
            nb1 = *(const float4*)(Bp2 + (size_t)64 * D);
        }
        // One m16n8k16 k-step covers the whole 16-wide slab.
        {
            uint32_t af[2][4];
#pragma unroll
            for (int mt = 0; mt < 2; ++mt) {
                const int m = warp_row * 32 + mt * 16;
                af[mt][0] = As[buf][m + qr][qc];          // k = 2qc,2qc+1
                af[mt][1] = As[buf][m + qr + 8][qc];
                af[mt][2] = As[buf][m + qr][qc + 4];      // k = 8+2qc
                af[mt][3] = As[buf][m + qr + 8][qc + 4];
            }
            uint32_t bf[8][2];
#pragma unroll
            for (int nt = 0; nt < 8; ++nt) {
                const int n = warp_col * 64 + nt * 8;
                bf[nt][0] = Bs[buf][n + qr][qc];
                bf[nt][1] = Bs[buf][n + qr][qc + 4];
            }
#pragma unroll
            for (int mt = 0; mt < 2; ++mt)
#pragma unroll
                for (int nt = 0; nt < 8; ++nt)
                    mma_bf16(C[mt][nt], af[mt][0], af[mt][1], af[mt][2],
                             af[mt][3], bf[nt][0], bf[nt][1]);
        }
        if (has_next) {
            buf ^= 1;
            uint32_t pa0 = f2bf16x2(na0.x, na0.y), pa1 = f2bf16x2(na0.z, na0.w);
            uint32_t pa2 = f2bf16x2(na1.x, na1.y), pa3 = f2bf16x2(na1.z, na1.w);
            uint32_t pb0 = f2bf16x2(nb0.x, nb0.y), pb1 = f2bf16x2(nb0.z, nb0.w);
            uint32_t pb2 = f2bf16x2(nb1.x, nb1.y), pb3 = f2bf16x2(nb1.z, nb1.w);
            __syncthreads();                 // all reads of buf^1 done
            As[buf][lrow][lp]          = pa0;
            As[buf][lrow][lp + 1]      = pa1;
            As[buf][lrow + 64][lp]     = pa2;
            As[buf][lrow + 64][lp + 1] = pa3;
            Bs[buf][lrow][lp]          = pb0;
            Bs[buf][lrow][lp + 1]      = pb1;
            Bs[buf][lrow + 64][lp]     = pb2;
            Bs[buf][lrow + 64][lp + 1] = pb3;
            __syncthreads();
        }
    }

    // ---- Epilogue --------------------------------------------------------
    __syncthreads();   // done with GEMM smem; overlay epilogue buffers
    float (*part)[128][8] = (float(*)[128][8])raw;          // [2][128][8] = 8192B
    float* SqI = (float*)(raw + 8192);                      // 128 floats
    float* SqJ = SqI + 128;                                 // 128 floats
    int*   TgI = (int*)(raw + 9216);                        // 128 ints
    int*   TgJ = TgI + 128;                                 // 128 ints

    if (tid < 128) { SqI[tid] = g_sq[i0 + tid]; TgI[tid] = T[i0 + tid]; }
    else { int r = tid - 128; SqJ[r] = g_sq[j0 + r]; TgJ[r] = T[j0 + r]; }
    __syncthreads();

    // Preload the 16 column attributes this thread touches.
    float sqj[16]; int tj[16]; int colv[16];
#pragma unroll
    for (int nt = 0; nt < 8; ++nt)
#pragma unroll
        for (int e = 0; e < 2; ++e) {
            const int c = warp_col * 64 + nt * 8 + qc * 2 + e;
            colv[nt * 2 + e] = c;
            sqj[nt * 2 + e] = SqJ[c];
            tj[nt * 2 + e] = TgJ[c];
        }

#pragma unroll
    for (int mt = 0; mt < 2; ++mt)
#pragma unroll
        for (int rh = 0; rh < 2; ++rh) {
            const int row = warp_row * 32 + mt * 16 + rh * 8 + qr;
            const int gi = i0 + row;
            const float sqi = SqI[row];
            const int ti = TgI[row];
            float posl = 0.f, negl = 0.f, poss = 0.f, negs = 0.f;
            float posd = 0.f, negd = 0.f, cnt = 0.f;
#pragma unroll
            for (int q = 0; q < 16; ++q) {
                const int nt = q >> 1, e = q & 1;
                const int gj = j0 + colv[q];
                if (gi == gj) continue;
                const float dot = C[mt][nt][rh * 2 + e];
                float d2 = sqi + sqj[q] - 2.f * dot;
                float dist = fast_sqrt(fmaxf(d2, 1e-12f));
                float ea = __expf(40.f * (1.f - dist));
                if (ti == tj[q]) {
                    posl += ea;
                    poss += __expf(20.f * (dist - 0.8f));
                    posd += dist;
                    cnt += 1.f;
                } else {
                    negl += ea;
                    negs += __expf(20.f * (1.1f - dist));
                    negd += dist;
                }
            }
#pragma unroll
            for (int o = 1; o <= 2; o <<= 1) {
                posl += __shfl_xor_sync(0xffffffffu, posl, o);
                negl += __shfl_xor_sync(0xffffffffu, negl, o);
                poss += __shfl_xor_sync(0xffffffffu, poss, o);
                negs += __shfl_xor_sync(0xffffffffu, negs, o);
                posd += __shfl_xor_sync(0xffffffffu, posd, o);
                negd += __shfl_xor_sync(0xffffffffu, negd, o);
                cnt  += __shfl_xor_sync(0xffffffffu, cnt,  o);
            }
            if (qc == 0) {
                part[warp_col][row][0] = posl;
                part[warp_col][row][1] = negl;
                part[warp_col][row][2] = poss;
                part[warp_col][row][3] = negs;
                part[warp_col][row][4] = posd;
                part[warp_col][row][5] = negd;
                part[warp_col][row][6] = cnt;
            }
        }
    __syncthreads();

    if (tid < 128) {
        const int row = tid;
        const int idx = blockIdx.x * N + (i0 + row);
        g_posl[idx] = part[0][row][0] + part[1][row][0];
        g_negl[idx] = part[0][row][1] + part[1][row][1];
        g_poss[idx] = part[0][row][2] + part[1][row][2];
        g_negs[idx] = part[0][row][3] + part[1][row][3];
        g_posd[idx] = part[0][row][4] + part[1][row][4];
        g_negd[idx] = part[0][row][5] + part[1][row][5];
        g_pcnt[idx] = part[0][row][6] + part[1][row][6];
    }
}

// ---------------------------------------------------------------------------
// Kernel 3a: per-row fold of the 32 column-block partials (16 blocks x 256).
// ---------------------------------------------------------------------------
__global__ void k_rows(void) {
    __shared__ double sh[4][8];
    const int i = blockIdx.x * 256 + threadIdx.x;   // row id, 0..4095

    float posl = 0.f, negl = 0.f, poss = 0.f, negs = 0.f;
    float posd = 0.f, negd = 0.f, cnt = 0.f;
#pragma unroll
    for (int c = 0; c < NCB; ++c) {
        const int idx = c * N + i;
        posl += g_posl[idx]; negl += g_negl[idx];
        poss += g_poss[idx]; negs += g_negs[idx];
        posd += g_posd[idx]; negd += g_negd[idx];
        cnt  += g_pcnt[idx];
    }
    float a_lr = 1.f - posl / (posl + negl);
    double lsum = (double)(a_lr * (logf(poss) + logf(negs)));
    double pd = (double)posd, nd = (double)negd, pc = (double)cnt;

#pragma unroll
    for (int o = 16; o; o >>= 1) {
        lsum += __shfl_xor_sync(0xffffffffu, lsum, o);
        pd   += __shfl_xor_sync(0xffffffffu, pd,   o);
        nd   += __shfl_xor_sync(0xffffffffu, nd,   o);
        pc   += __shfl_xor_sync(0xffffffffu, pc,   o);
    }
    const int lane = threadIdx.x & 31;
    const int w    = threadIdx.x >> 5;
    if (lane == 0) { sh[0][w] = lsum; sh[1][w] = pd; sh[2][w] = nd; sh[3][w] = pc; }
    __syncthreads();
    if (threadIdx.x == 0) {
        double L = 0.0, P = 0.0, Nd = 0.0, Pc = 0.0;
#pragma unroll
        for (int k = 0; k < 8; ++k) {
            L += sh[0][k]; P += sh[1][k]; Nd += sh[2][k]; Pc += sh[3][k];
        }
        g_blk[blockIdx.x][0] = L;
        g_blk[blockIdx.x][1] = P;
        g_blk[blockIdx.x][2] = Nd;
        g_blk[blockIdx.x][3] = Pc;
    }
}

// ---------------------------------------------------------------------------
// Kernel 3b: fold the 16 block partials, write out[4].
// ---------------------------------------------------------------------------
__global__ void k_final4(float* __restrict__ out) {
    if (threadIdx.x == 0) {
        double L = 0.0, P = 0.0, Nd = 0.0, Pc = 0.0;
#pragma unroll
        for (int k = 0; k < NRB; ++k) {
            L += g_blk[k][0]; P += g_blk[k][1]; Nd += g_blk[k][2]; Pc += g_blk[k][3];
        }
        double negcnt = (double)N * (double)(N - 1) - Pc;
        out[0] = (float)(L / (double)N);
        out[1] = 0.f;
        out[2] = (float)(P / Pc);
        out[3] = (float)(Nd / negcnt);
    }
}

// ---------------------------------------------------------------------------
extern "C" void kernel_launch(void* const* d_in, const int* in_sizes, int n_in,
                              void* d_out, int out_size) {
    const float* X = (const float*)d_in[0];   // [4096,1024] fp32, L2-normalized
    const int*   T = (const int*)d_in[1];     // [4096] int32 targets
    float* out = (float*)d_out;               // [4] fp32

    k_sq<<<N / 8, 256>>>(X);
    dim3 grid(NCB, NCB);
    k_main<<<grid, 256>>>(X, T);
    k_rows<<<NRB, 256>>>();
    k_final4<<<1, 32>>>(out);
}